// round 14
// baseline (speedup 1.0000x reference)
#include <cuda_runtime.h>
#include <cstdint>

// y[t,b,f] = sum_{k=0..20} x[t+k,b,f] * w[f,k], zero-padded past t=T-1.
// Thread owns two adjacent features (one float2 column) and a 64-long time
// strip: 16 fully-unrolled chunks of 4 with a 20-element carried register
// window and a one-chunk-ahead load pipeline (nxt[]).
//
// KEY CHANGE vs prior rounds: weights live in a PRIVATE smem array (written
// and read by the same thread -> no barriers, no conflicts) and the compute
// loop is tap-outer (one LDS.64 weight per tap, applied to 4 accumulators).
// This cuts live registers from ~126 to ~80, allowing 3 CTAs/SM (24 warps)
// under __launch_bounds__(256,3) — the latency-hiding the last 4 rounds
// showed we were missing. Packed fma.rn.f32x2 halves fp32 work.

#define FMA_F32X2(d, a, b, c) \
    asm("fma.rn.f32x2 %0, %1, %2, %3;" : "=l"(d) : "l"(a), "l"(b), "l"(c))
#define MUL_F32X2(d, a, b) \
    asm("mul.rn.f32x2 %0, %1, %2;" : "=l"(d) : "l"(a), "l"(b))

namespace la {
constexpr int T = 2048;
constexpr int B = 16;
constexpr int F = 1024;
constexpr int CTX = 20;
constexpr int K = 21;                  // CTX + 1 taps
constexpr int BF2 = (B * F) / 2;       // timestep stride in float2 units = 8192
constexpr int TCHUNK = 64;             // t's per thread
constexpr int STEP = 4;                // t's per inner chunk (small => low regs)
constexpr int NCHUNK = TCHUNK / STEP;  // 16, fully unrolled
constexpr int NTHR = 256;
}  // namespace la

__global__ void __launch_bounds__(256, 3)
lookahead_kernel(const unsigned long long* __restrict__ x2,  // x as float2 (u64 bits)
                 const float* __restrict__ w,
                 unsigned long long* __restrict__ y2)
{
    using namespace la;
    // Per-thread private weight store: sw[k*NTHR + tid]. Same thread writes
    // and reads -> no synchronization needed. 21*256*8 = 43008 B per CTA.
    __shared__ unsigned long long sw[K * NTHR];

    const int tid   = threadIdx.x;
    const int fpair = blockIdx.x * blockDim.x + tid;          // 0..511
    const int b     = blockIdx.y;                             // 0..15
    const int t0    = blockIdx.z * TCHUNK;                    // 0,64,...,1984
    const int f0    = fpair * 2;

    // Stage packed weight pairs (lo = f0, hi = f0+1) into smem. One-time cost;
    // w is 84 KB and L2-resident after the first wave.
#pragma unroll
    for (int k = 0; k < K; k++) {
        const unsigned int lo = __float_as_uint(__ldg(&w[(size_t)f0 * K + k]));
        const unsigned int hi = __float_as_uint(__ldg(&w[(size_t)(f0 + 1) * K + k]));
        sw[k * NTHR + tid] = (unsigned long long)lo | ((unsigned long long)hi << 32);
    }

    const unsigned long long* __restrict__ xp = x2 + (size_t)b * (F / 2) + fpair;
    unsigned long long* __restrict__       yp = y2 + (size_t)b * (F / 2) + fpair;

    // win[0..23]: window for the CURRENT chunk (t = tb .. tb+23).
    // nxt[0..3]:  in-flight loads for the NEXT chunk.
    unsigned long long win[STEP + CTX];
    unsigned long long nxt[STEP];

    // Prologue: chunk 0's full window, t0 .. t0+23 (max 2007 < T).
#pragma unroll
    for (int i = 0; i < STEP + CTX; i++)
        win[i] = __ldg(&xp[(size_t)(t0 + i) * BF2]);

#pragma unroll
    for (int c = 0; c < NCHUNK; c++) {
        const int tb = t0 + c * STEP;

        // Issue next chunk's 4 loads first — consumed only after this chunk's
        // full FMA block, so DRAM latency overlaps compute across 24 warps.
        if (c + 1 < NCHUNK) {
#pragma unroll
            for (int i = 0; i < STEP; i++) {
                const int t = tb + STEP + CTX + i;
                nxt[i] = (t < T) ? __ldg(&xp[(size_t)t * BF2]) : 0ULL;
            }
        }

        // Tap-outer compute: 4 accumulators, one weight LDS per tap.
        unsigned long long acc[STEP];
        {
            const unsigned long long wk0 = sw[tid];
#pragma unroll
            for (int i = 0; i < STEP; i++)
                MUL_F32X2(acc[i], win[i], wk0);
        }
#pragma unroll
        for (int k = 1; k < K; k++) {
            const unsigned long long wkk = sw[k * NTHR + tid];
#pragma unroll
            for (int i = 0; i < STEP; i++)
                FMA_F32X2(acc[i], win[i + k], wkk, acc[i]);
        }
#pragma unroll
        for (int i = 0; i < STEP; i++)
            __stcs(&yp[(size_t)(tb + i) * BF2], acc[i]);

        // Rotate window and merge pipelined loads (renaming under full unroll).
        if (c + 1 < NCHUNK) {
#pragma unroll
            for (int i = 0; i < CTX; i++)
                win[i] = win[STEP + i];
#pragma unroll
            for (int i = 0; i < STEP; i++)
                win[CTX + i] = nxt[i];
        }
    }
}

extern "C" void kernel_launch(void* const* d_in, const int* in_sizes, int n_in,
                              void* d_out, int out_size)
{
    using namespace la;
    (void)in_sizes; (void)n_in; (void)out_size;
    const unsigned long long* x2 = (const unsigned long long*)d_in[0];  // x: (T,B,F) f32
    const float*              w  = (const float*)d_in[1];               // weight: (F,21) f32
    // d_in[2] = tail_padding (int, ==1): baked into the zero-fill guard.
    unsigned long long* y2 = (unsigned long long*)d_out;                // y: (T,B,F) f32

    dim3 block(NTHR, 1, 1);
    dim3 grid((F / 2) / NTHR, B, T / TCHUNK);  // (2, 16, 32) = 1024 blocks
    lookahead_kernel<<<grid, block>>>(x2, w, y2);
}

// round 15
// speedup vs baseline: 1.9429x; 1.9429x over previous
#include <cuda_runtime.h>
#include <cstdint>

// y[t,b,f] = sum_{k=0..20} x[t+k,b,f] * w[f,k], zero-padded past t=T-1.
// Thread owns two adjacent features (one float2 column) and a 64-long time
// strip: 8 fully-unrolled chunks of 8 with a 20-element carried register
// window. Weights stay in registers (R14 proved smem weights serialize).
//
// KEY CHANGE: two-phase FMA schedule per chunk.
//   Phase 1: all taps with i+k < CTX  -> touch only the CARRIED window
//            (132 FMA2s ~ 264 issue cycles of fresh-load-free work).
//   Phase 2: taps ordered by fresh index j=i+k ascending -> consumption
//            order == load issue order, so each fresh load is covered by
//            phase 1 + earlier phase-2 work across 4 warps/SMSP.
// This hides DRAM latency with ZERO extra registers or instructions —
// pure scheduling. Packed fma.rn.f32x2 halves fp32 work; streaming stores.

#define FMA_F32X2(d, a, b, c) \
    asm("fma.rn.f32x2 %0, %1, %2, %3;" : "=l"(d) : "l"(a), "l"(b), "l"(c))
#define MUL_F32X2(d, a, b) \
    asm("mul.rn.f32x2 %0, %1, %2;" : "=l"(d) : "l"(a), "l"(b))

namespace la {
constexpr int T = 2048;
constexpr int B = 16;
constexpr int F = 1024;
constexpr int CTX = 20;
constexpr int K = 21;                  // CTX + 1 taps
constexpr int BF2 = (B * F) / 2;       // timestep stride in float2 units = 8192
constexpr int TCHUNK = 64;             // t's per thread
constexpr int STEP = 8;                // t's per inner chunk
constexpr int NCHUNK = TCHUNK / STEP;  // 8, fully unrolled
constexpr int NTHR = 256;
}  // namespace la

__global__ void __launch_bounds__(256, 2)
lookahead_kernel(const unsigned long long* __restrict__ x2,  // x as float2 (u64 bits)
                 const float* __restrict__ w,
                 unsigned long long* __restrict__ y2)
{
    using namespace la;
    const int tid   = threadIdx.x;
    const int fpair = blockIdx.x * blockDim.x + tid;          // 0..511
    const int b     = blockIdx.y;                             // 0..15
    const int t0    = blockIdx.z * TCHUNK;                    // 0,64,...,1984
    const int f0    = fpair * 2;

    // Pack the two per-feature weight vectors into u64 (lo = f0, hi = f0+1),
    // matching the float2 load layout (.x in low word). Registers, not smem.
    unsigned long long wk[K];
#pragma unroll
    for (int k = 0; k < K; k++) {
        const unsigned int lo = __float_as_uint(__ldg(&w[(size_t)f0 * K + k]));
        const unsigned int hi = __float_as_uint(__ldg(&w[(size_t)(f0 + 1) * K + k]));
        wk[k] = (unsigned long long)lo | ((unsigned long long)hi << 32);
    }

    const unsigned long long* __restrict__ xp = x2 + (size_t)b * (F / 2) + fpair;
    unsigned long long* __restrict__       yp = y2 + (size_t)b * (F / 2) + fpair;

    // win[0..19]: carried window; win[20..27]: fresh loads for this chunk.
    unsigned long long win[STEP + CTX];

    // Preload first CTX timesteps (t0+19 <= 2003 < T: always in-bounds).
#pragma unroll
    for (int i = 0; i < CTX; i++)
        win[i] = __ldg(&xp[(size_t)(t0 + i) * BF2]);

#pragma unroll
    for (int c = 0; c < NCHUNK; c++) {
        const int tb = t0 + c * STEP;

        // Issue this chunk's 8 fresh loads up front (MLP=8, fire-and-forget —
        // nothing below touches them until phase 2).
#pragma unroll
        for (int i = 0; i < STEP; i++) {
            const int t = tb + CTX + i;
            win[CTX + i] = (t < T) ? __ldg(&xp[(size_t)t * BF2]) : 0ULL;
        }

        unsigned long long acc[STEP];

        // ---- Phase 1: carried-window taps only (i + k < CTX). ----
#pragma unroll
        for (int i = 0; i < STEP; i++)
            MUL_F32X2(acc[i], win[i], wk[0]);          // k=0: i < CTX always
#pragma unroll
        for (int k = 1; k < K; k++) {
#pragma unroll
            for (int i = 0; i < STEP; i++) {
                if (i + k < CTX)
                    FMA_F32X2(acc[i], win[i + k], wk[k], acc[i]);
            }
        }

        // ---- Phase 2: fresh taps, ordered by fresh index j (= load order). ----
#pragma unroll
        for (int j = CTX; j < CTX + STEP; j++) {
#pragma unroll
            for (int i = 0; i < STEP; i++) {
                const int k = j - i;
                if (k >= 1 && k < K)                    // i >= j-CTX guaranteed
                    FMA_F32X2(acc[i], win[j], wk[k], acc[i]);
            }
        }

        // Stores (streaming: keep L2 for the read stream).
#pragma unroll
        for (int i = 0; i < STEP; i++)
            __stcs(&yp[(size_t)(tb + i) * BF2], acc[i]);

        // Rotate carried window — pure renaming under full unroll.
#pragma unroll
        for (int i = 0; i < CTX; i++)
            win[i] = win[STEP + i];
    }
}

extern "C" void kernel_launch(void* const* d_in, const int* in_sizes, int n_in,
                              void* d_out, int out_size)
{
    using namespace la;
    (void)in_sizes; (void)n_in; (void)out_size;
    const unsigned long long* x2 = (const unsigned long long*)d_in[0];  // x: (T,B,F) f32
    const float*              w  = (const float*)d_in[1];               // weight: (F,21) f32
    // d_in[2] = tail_padding (int, ==1): baked into the zero-fill guard.
    unsigned long long* y2 = (unsigned long long*)d_out;                // y: (T,B,F) f32

    dim3 block(NTHR, 1, 1);
    dim3 grid((F / 2) / NTHR, B, T / TCHUNK);  // (2, 16, 32) = 1024 blocks
    lookahead_kernel<<<grid, block>>>(x2, w, y2);
}